// round 1
// baseline (speedup 1.0000x reference)
#include <cuda_runtime.h>
#include <cuda_bf16.h>
#include <cstddef>

// Problem constants (fixed shapes for this problem)
#define T_TOK 2048
#define H_DIM 2048
#define N_EXP 32
#define I_DIM 768
#define TOPK  8

// -------- device scratch (static; no runtime allocation) ------------------
__device__ int   g_cnt[N_EXP];                  // tokens per expert
__device__ int   g_list[N_EXP * T_TOK];         // packed token*8+slot per expert
__device__ float g_rw[T_TOK * TOPK];            // routing weight per (token,slot)
__device__ float g_h[(size_t)T_TOK * TOPK * I_DIM];  // 50.3 MB intermediate h

// -------- init: zero output + counters ------------------------------------
__global__ void init_kernel(float* __restrict__ out, int n)
{
    int i = blockIdx.x * 256 + threadIdx.x;
    if (i < N_EXP) g_cnt[i] = 0;
    for (int j = i; j < n; j += gridDim.x * 256) out[j] = 0.f;
}

// -------- router: logits, top-8, softmax, scatter --------------------------
__global__ __launch_bounds__(256) void router_kernel(
    const float* __restrict__ x, const float* __restrict__ gw)
{
    __shared__ float xs[H_DIM];
    __shared__ float logits[N_EXP];

    const int t = blockIdx.x;
    const float* xr = x + (size_t)t * H_DIM;
    for (int i = threadIdx.x; i < H_DIM; i += 256) xs[i] = xr[i];
    __syncthreads();

    const int warp = threadIdx.x >> 5;
    const int lane = threadIdx.x & 31;

    float acc[4] = {0.f, 0.f, 0.f, 0.f};
    for (int k = lane; k < H_DIM; k += 32) {
        float xv = xs[k];
        #pragma unroll
        for (int q = 0; q < 4; q++)
            acc[q] = fmaf(xv, gw[(size_t)(warp * 4 + q) * H_DIM + k], acc[q]);
    }
    #pragma unroll
    for (int q = 0; q < 4; q++) {
        float v = acc[q];
        #pragma unroll
        for (int off = 16; off; off >>= 1)
            v += __shfl_down_sync(0xffffffffu, v, off);
        if (lane == 0) logits[warp * 4 + q] = v;
    }
    __syncthreads();

    if (threadIdx.x == 0) {
        float lg[N_EXP];
        #pragma unroll
        for (int i = 0; i < N_EXP; i++) lg[i] = logits[i];

        int   sel[TOPK];
        float sv[TOPK];
        #pragma unroll
        for (int s = 0; s < TOPK; s++) {
            int best = 0; float bv = -3.4e38f;
            #pragma unroll
            for (int i = 0; i < N_EXP; i++)
                if (lg[i] > bv) { bv = lg[i]; best = i; }
            sel[s] = best; sv[s] = bv; lg[best] = -3.4e38f;
        }
        float mx = sv[0];
        float ex[TOPK], sum = 0.f;
        #pragma unroll
        for (int s = 0; s < TOPK; s++) { ex[s] = __expf(sv[s] - mx); sum += ex[s]; }
        float inv = 1.f / sum;
        #pragma unroll
        for (int s = 0; s < TOPK; s++) {
            int e = sel[s];
            int pos = atomicAdd(&g_cnt[e], 1);
            g_list[e * T_TOK + pos] = t * TOPK + s;
            g_rw[t * TOPK + s] = ex[s] * inv;
        }
    }
}

// -------- phase A: per-expert  h = silu(x@Wg^T) * (x@Wu^T) * route_w -------
// tile 64x64, K-step 16, 4x4 per thread (256 threads)
__global__ __launch_bounds__(256) void phaseA_kernel(
    const float* __restrict__ x,
    const float* __restrict__ wg,
    const float* __restrict__ wu)
{
    const int e    = blockIdx.z;
    const int cnt  = g_cnt[e];
    const int row0 = blockIdx.x * 64;
    if (row0 >= cnt) return;
    const int col0 = blockIdx.y * 64;

    __shared__ float Xs[16][65];
    __shared__ float Gs[16][65];
    __shared__ float Us[16][65];
    __shared__ int   toks[64];

    const int tid = threadIdx.x;
    if (tid < 64) {
        int r = row0 + tid;
        toks[tid] = (r < cnt) ? g_list[e * T_TOK + r] : -1;
    }
    __syncthreads();

    const int tx = tid & 15;
    const int ty = tid >> 4;

    float accG[4][4] = {};
    float accU[4][4] = {};

    const float* wgE = wg + (size_t)e * I_DIM * H_DIM + (size_t)col0 * H_DIM;
    const float* wuE = wu + (size_t)e * I_DIM * H_DIM + (size_t)col0 * H_DIM;

    for (int k0 = 0; k0 < H_DIM; k0 += 16) {
        #pragma unroll
        for (int j = 0; j < 4; j++) {
            int l = j * 256 + tid;
            int m = l >> 4;
            int k = l & 15;
            int pk = toks[m];
            Xs[k][m] = (pk >= 0) ? x[(size_t)(pk >> 3) * H_DIM + k0 + k] : 0.f;
            Gs[k][m] = wgE[(size_t)m * H_DIM + k0 + k];
            Us[k][m] = wuE[(size_t)m * H_DIM + k0 + k];
        }
        __syncthreads();
        #pragma unroll
        for (int kk = 0; kk < 16; kk++) {
            float a[4], bg[4], bu[4];
            #pragma unroll
            for (int i = 0; i < 4; i++) a[i] = Xs[kk][ty * 4 + i];
            #pragma unroll
            for (int j = 0; j < 4; j++) { bg[j] = Gs[kk][tx * 4 + j]; bu[j] = Us[kk][tx * 4 + j]; }
            #pragma unroll
            for (int i = 0; i < 4; i++)
                #pragma unroll
                for (int j = 0; j < 4; j++) {
                    accG[i][j] = fmaf(a[i], bg[j], accG[i][j]);
                    accU[i][j] = fmaf(a[i], bu[j], accU[i][j]);
                }
        }
        __syncthreads();
    }

    #pragma unroll
    for (int i = 0; i < 4; i++) {
        int m = ty * 4 + i;
        int pk = toks[m];
        if (pk < 0) continue;
        float w = g_rw[pk];
        float* hrow = g_h + (size_t)pk * I_DIM + col0 + tx * 4;
        #pragma unroll
        for (int j = 0; j < 4; j++) {
            float g = accG[i][j];
            float u = accU[i][j];
            float s = g / (1.f + __expf(-g));   // silu
            hrow[j] = s * u * w;
        }
    }
}

// -------- phase B: out[t] += h @ Wd^T  (atomic scatter-add) ----------------
__global__ __launch_bounds__(256) void phaseB_kernel(
    const float* __restrict__ wd, float* __restrict__ out)
{
    const int e    = blockIdx.z;
    const int cnt  = g_cnt[e];
    const int row0 = blockIdx.x * 64;
    if (row0 >= cnt) return;
    const int col0 = blockIdx.y * 64;   // H column

    __shared__ float Hs[16][65];
    __shared__ float Ds[16][65];
    __shared__ int   toks[64];

    const int tid = threadIdx.x;
    if (tid < 64) {
        int r = row0 + tid;
        toks[tid] = (r < cnt) ? g_list[e * T_TOK + r] : -1;
    }
    __syncthreads();

    const int tx = tid & 15;
    const int ty = tid >> 4;

    float acc[4][4] = {};

    const float* wdE = wd + (size_t)e * H_DIM * I_DIM + (size_t)col0 * I_DIM;

    for (int k0 = 0; k0 < I_DIM; k0 += 16) {
        #pragma unroll
        for (int j = 0; j < 4; j++) {
            int l = j * 256 + tid;
            int m = l >> 4;
            int k = l & 15;
            int pk = toks[m];
            Hs[k][m] = (pk >= 0) ? g_h[(size_t)pk * I_DIM + k0 + k] : 0.f;
            Ds[k][m] = wdE[(size_t)m * I_DIM + k0 + k];
        }
        __syncthreads();
        #pragma unroll
        for (int kk = 0; kk < 16; kk++) {
            float a[4], b[4];
            #pragma unroll
            for (int i = 0; i < 4; i++) a[i] = Hs[kk][ty * 4 + i];
            #pragma unroll
            for (int j = 0; j < 4; j++) b[j] = Ds[kk][tx * 4 + j];
            #pragma unroll
            for (int i = 0; i < 4; i++)
                #pragma unroll
                for (int j = 0; j < 4; j++)
                    acc[i][j] = fmaf(a[i], b[j], acc[i][j]);
        }
        __syncthreads();
    }

    #pragma unroll
    for (int i = 0; i < 4; i++) {
        int m = ty * 4 + i;
        int pk = toks[m];
        if (pk < 0) continue;
        float* orow = out + (size_t)(pk >> 3) * H_DIM + col0 + tx * 4;
        #pragma unroll
        for (int j = 0; j < 4; j++)
            atomicAdd(&orow[j], acc[i][j]);
    }
}

// ---------------------------------------------------------------------------
extern "C" void kernel_launch(void* const* d_in, const int* in_sizes, int n_in,
                              void* d_out, int out_size)
{
    const float* x  = (const float*)d_in[0];   // [1,2048,2048]
    const float* gw = (const float*)d_in[1];   // [32,2048]
    const float* wg = (const float*)d_in[2];   // [32,768,2048]
    const float* wu = (const float*)d_in[3];   // [32,768,2048]
    const float* wd = (const float*)d_in[4];   // [32,2048,768]
    float* out = (float*)d_out;                // [1,2048,2048] f32

    init_kernel<<<1024, 256>>>(out, out_size);
    router_kernel<<<T_TOK, 256>>>(x, gw);
    phaseA_kernel<<<dim3(T_TOK / 64, I_DIM / 64, N_EXP), 256>>>(x, wg, wu);
    phaseB_kernel<<<dim3(T_TOK / 64, H_DIM / 64, N_EXP), 256>>>(wd, out);
}

// round 2
// speedup vs baseline: 2.4213x; 2.4213x over previous
#include <cuda_runtime.h>
#include <cstddef>
#include <cstdint>

#define T_TOK 2048
#define H_DIM 2048
#define N_EXP 32
#define I_DIM 768
#define TOPK  8

// -------- static device scratch --------------------------------------------
__device__ int   g_cnt[N_EXP];
__device__ int   g_list[N_EXP * T_TOK];               // packed token*8+slot
__device__ float g_rw[T_TOK * TOPK];
__device__ float g_h[(size_t)T_TOK * TOPK * I_DIM];   // 50 MB intermediate
__device__ float g_o[(size_t)T_TOK * TOPK * H_DIM];   // 134 MB per-slot down-proj

// -------- helpers -----------------------------------------------------------
__device__ __forceinline__ uint32_t f2tf32(float x) {
    uint32_t r;
    asm("cvt.rna.tf32.f32 %0, %1;" : "=r"(r) : "f"(x));
    return r;
}

__device__ __forceinline__ void mma_tf32(float d[4], const uint32_t a[4], const uint32_t b[2]) {
    asm volatile(
        "mma.sync.aligned.m16n8k8.row.col.f32.tf32.tf32.f32 "
        "{%0,%1,%2,%3},{%4,%5,%6,%7},{%8,%9},{%0,%1,%2,%3};"
        : "+f"(d[0]), "+f"(d[1]), "+f"(d[2]), "+f"(d[3])
        : "r"(a[0]), "r"(a[1]), "r"(a[2]), "r"(a[3]), "r"(b[0]), "r"(b[1]));
}

// -------- init: zero expert counters ----------------------------------------
__global__ void init_kernel()
{
    if (threadIdx.x < N_EXP) g_cnt[threadIdx.x] = 0;
}

// -------- router: logits, top-8, softmax, scatter ----------------------------
__global__ __launch_bounds__(256) void router_kernel(
    const float* __restrict__ x, const float* __restrict__ gw)
{
    __shared__ float xs[H_DIM];
    __shared__ float logits[N_EXP];

    const int t = blockIdx.x;
    const float* xr = x + (size_t)t * H_DIM;
    for (int i = threadIdx.x; i < H_DIM; i += 256) xs[i] = xr[i];
    __syncthreads();

    const int warp = threadIdx.x >> 5;
    const int lane = threadIdx.x & 31;

    float acc[4] = {0.f, 0.f, 0.f, 0.f};
    for (int k = lane; k < H_DIM; k += 32) {
        float xv = xs[k];
        #pragma unroll
        for (int q = 0; q < 4; q++)
            acc[q] = fmaf(xv, gw[(size_t)(warp * 4 + q) * H_DIM + k], acc[q]);
    }
    #pragma unroll
    for (int q = 0; q < 4; q++) {
        float v = acc[q];
        #pragma unroll
        for (int off = 16; off; off >>= 1)
            v += __shfl_down_sync(0xffffffffu, v, off);
        if (lane == 0) logits[warp * 4 + q] = v;
    }
    __syncthreads();

    if (threadIdx.x == 0) {
        float lg[N_EXP];
        #pragma unroll
        for (int i = 0; i < N_EXP; i++) lg[i] = logits[i];

        int   sel[TOPK];
        float sv[TOPK];
        #pragma unroll
        for (int s = 0; s < TOPK; s++) {
            int best = 0; float bv = -3.4e38f;
            #pragma unroll
            for (int i = 0; i < N_EXP; i++)
                if (lg[i] > bv) { bv = lg[i]; best = i; }
            sel[s] = best; sv[s] = bv; lg[best] = -3.4e38f;
        }
        float mx = sv[0];
        float ex[TOPK], sum = 0.f;
        #pragma unroll
        for (int s = 0; s < TOPK; s++) { ex[s] = __expf(sv[s] - mx); sum += ex[s]; }
        float inv = 1.f / sum;
        #pragma unroll
        for (int s = 0; s < TOPK; s++) {
            int e = sel[s];
            int pos = atomicAdd(&g_cnt[e], 1);
            g_list[e * T_TOK + pos] = t * TOPK + s;
            g_rw[t * TOPK + s] = ex[s] * inv;
        }
    }
}

// ============================================================================
// phase A: h = silu(x@Wg^T) * (x@Wu^T) * route_w     (tf32 tensor-core GEMM)
// BM=128, BN=64, BK=32; 8 warps as 4(M)x2(N); warp tile 32x32 (m16n8k8)
// ============================================================================
__global__ __launch_bounds__(256) void phaseA_kernel(
    const float* __restrict__ x,
    const float* __restrict__ wg,
    const float* __restrict__ wu)
{
    const int e    = blockIdx.z;
    const int cnt  = g_cnt[e];
    const int row0 = blockIdx.x * 128;
    if (row0 >= cnt) return;
    const int col0 = blockIdx.y * 64;

    __shared__ uint32_t Xs[32][136];   // [k][m]
    __shared__ uint32_t Gs[32][72];    // [k][n]
    __shared__ uint32_t Us[32][72];
    __shared__ int      toks[128];

    const int tid = threadIdx.x;
    if (tid < 128) {
        int r = row0 + tid;
        toks[tid] = (r < cnt) ? g_list[e * T_TOK + r] : -1;
    }
    __syncthreads();

    const int warp  = tid >> 5;
    const int lane  = tid & 31;
    const int warpM = warp & 3;      // 0..3
    const int warpN = warp >> 2;     // 0..1
    const int gid   = lane >> 2;     // 0..7
    const int tcol  = lane & 3;      // 0..3
    const int mw0   = warpM * 32;
    const int nw0   = warpN * 32;

    float accG[2][4][4] = {};
    float accU[2][4][4] = {};

    const float* wgE = wg + (size_t)e * I_DIM * H_DIM + (size_t)col0 * H_DIM;
    const float* wuE = wu + (size_t)e * I_DIM * H_DIM + (size_t)col0 * H_DIM;

    for (int k0 = 0; k0 < H_DIM; k0 += 32) {
        // ---- stage X (128x32) ----
        #pragma unroll
        for (int i = 0; i < 4; i++) {
            int flat = i * 256 + tid;        // 0..1023
            int m  = flat & 127;
            int kg = flat >> 7;              // 0..7
            int pk = toks[m];
            float4 v = make_float4(0.f, 0.f, 0.f, 0.f);
            if (pk >= 0)
                v = *(const float4*)&x[(size_t)(pk >> 3) * H_DIM + k0 + kg * 4];
            Xs[kg * 4 + 0][m] = f2tf32(v.x);
            Xs[kg * 4 + 1][m] = f2tf32(v.y);
            Xs[kg * 4 + 2][m] = f2tf32(v.z);
            Xs[kg * 4 + 3][m] = f2tf32(v.w);
        }
        // ---- stage Wg, Wu (64x32 each) ----
        #pragma unroll
        for (int i = 0; i < 2; i++) {
            int flat = i * 256 + tid;        // 0..511
            int n  = flat & 63;
            int kg = flat >> 6;              // 0..7
            float4 vg = *(const float4*)&wgE[(size_t)n * H_DIM + k0 + kg * 4];
            Gs[kg * 4 + 0][n] = f2tf32(vg.x);
            Gs[kg * 4 + 1][n] = f2tf32(vg.y);
            Gs[kg * 4 + 2][n] = f2tf32(vg.z);
            Gs[kg * 4 + 3][n] = f2tf32(vg.w);
            float4 vu = *(const float4*)&wuE[(size_t)n * H_DIM + k0 + kg * 4];
            Us[kg * 4 + 0][n] = f2tf32(vu.x);
            Us[kg * 4 + 1][n] = f2tf32(vu.y);
            Us[kg * 4 + 2][n] = f2tf32(vu.z);
            Us[kg * 4 + 3][n] = f2tf32(vu.w);
        }
        __syncthreads();

        // ---- compute: 4 k-steps of 8 ----
        #pragma unroll
        for (int ks = 0; ks < 4; ks++) {
            const int kk = ks * 8;
            uint32_t a[2][4];
            #pragma unroll
            for (int mf = 0; mf < 2; mf++) {
                int r = mw0 + mf * 16 + gid;
                a[mf][0] = Xs[kk + tcol][r];
                a[mf][1] = Xs[kk + tcol][r + 8];
                a[mf][2] = Xs[kk + tcol + 4][r];
                a[mf][3] = Xs[kk + tcol + 4][r + 8];
            }
            #pragma unroll
            for (int nf = 0; nf < 4; nf++) {
                int c = nw0 + nf * 8 + gid;
                uint32_t bg[2], bu[2];
                bg[0] = Gs[kk + tcol][c];
                bg[1] = Gs[kk + tcol + 4][c];
                bu[0] = Us[kk + tcol][c];
                bu[1] = Us[kk + tcol + 4][c];
                #pragma unroll
                for (int mf = 0; mf < 2; mf++) {
                    mma_tf32(accG[mf][nf], a[mf], bg);
                    mma_tf32(accU[mf][nf], a[mf], bu);
                }
            }
        }
        __syncthreads();
    }

    // ---- epilogue: silu(g)*u*rw -> g_h ----
    #pragma unroll
    for (int mf = 0; mf < 2; mf++) {
        #pragma unroll
        for (int half = 0; half < 2; half++) {
            int rl = mw0 + mf * 16 + gid + half * 8;
            int pk = toks[rl];
            if (pk < 0) continue;
            float w = g_rw[pk];
            #pragma unroll
            for (int nf = 0; nf < 4; nf++) {
                int col = col0 + nw0 + nf * 8 + 2 * tcol;
                float g0 = accG[mf][nf][half * 2 + 0];
                float g1 = accG[mf][nf][half * 2 + 1];
                float u0 = accU[mf][nf][half * 2 + 0];
                float u1 = accU[mf][nf][half * 2 + 1];
                float2 o;
                o.x = (g0 / (1.f + __expf(-g0))) * u0 * w;
                o.y = (g1 / (1.f + __expf(-g1))) * u1 * w;
                *(float2*)&g_h[(size_t)pk * I_DIM + col] = o;
            }
        }
    }
}

// ============================================================================
// phase B: g_o[pk] = h[pk] @ Wd[e]^T    (tf32 GEMM, exact per-row store)
// BM=128, BN=64, BK=32; K=768
// ============================================================================
__global__ __launch_bounds__(256) void phaseB_kernel(
    const float* __restrict__ wd)
{
    const int e    = blockIdx.z;
    const int cnt  = g_cnt[e];
    const int row0 = blockIdx.x * 128;
    if (row0 >= cnt) return;
    const int col0 = blockIdx.y * 64;   // H column

    __shared__ uint32_t Hs[32][136];
    __shared__ uint32_t Ds[32][72];
    __shared__ int      toks[128];

    const int tid = threadIdx.x;
    if (tid < 128) {
        int r = row0 + tid;
        toks[tid] = (r < cnt) ? g_list[e * T_TOK + r] : -1;
    }
    __syncthreads();

    const int warp  = tid >> 5;
    const int lane  = tid & 31;
    const int warpM = warp & 3;
    const int warpN = warp >> 2;
    const int gid   = lane >> 2;
    const int tcol  = lane & 3;
    const int mw0   = warpM * 32;
    const int nw0   = warpN * 32;

    float acc[2][4][4] = {};

    const float* wdE = wd + (size_t)e * H_DIM * I_DIM + (size_t)col0 * I_DIM;

    for (int k0 = 0; k0 < I_DIM; k0 += 32) {
        #pragma unroll
        for (int i = 0; i < 4; i++) {
            int flat = i * 256 + tid;
            int m  = flat & 127;
            int kg = flat >> 7;
            int pk = toks[m];
            float4 v = make_float4(0.f, 0.f, 0.f, 0.f);
            if (pk >= 0)
                v = *(const float4*)&g_h[(size_t)pk * I_DIM + k0 + kg * 4];
            Hs[kg * 4 + 0][m] = f2tf32(v.x);
            Hs[kg * 4 + 1][m] = f2tf32(v.y);
            Hs[kg * 4 + 2][m] = f2tf32(v.z);
            Hs[kg * 4 + 3][m] = f2tf32(v.w);
        }
        #pragma unroll
        for (int i = 0; i < 2; i++) {
            int flat = i * 256 + tid;
            int n  = flat & 63;
            int kg = flat >> 6;
            float4 v = *(const float4*)&wdE[(size_t)n * I_DIM + k0 + kg * 4];
            Ds[kg * 4 + 0][n] = f2tf32(v.x);
            Ds[kg * 4 + 1][n] = f2tf32(v.y);
            Ds[kg * 4 + 2][n] = f2tf32(v.z);
            Ds[kg * 4 + 3][n] = f2tf32(v.w);
        }
        __syncthreads();

        #pragma unroll
        for (int ks = 0; ks < 4; ks++) {
            const int kk = ks * 8;
            uint32_t a[2][4];
            #pragma unroll
            for (int mf = 0; mf < 2; mf++) {
                int r = mw0 + mf * 16 + gid;
                a[mf][0] = Hs[kk + tcol][r];
                a[mf][1] = Hs[kk + tcol][r + 8];
                a[mf][2] = Hs[kk + tcol + 4][r];
                a[mf][3] = Hs[kk + tcol + 4][r + 8];
            }
            #pragma unroll
            for (int nf = 0; nf < 4; nf++) {
                int c = nw0 + nf * 8 + gid;
                uint32_t b[2];
                b[0] = Ds[kk + tcol][c];
                b[1] = Ds[kk + tcol + 4][c];
                #pragma unroll
                for (int mf = 0; mf < 2; mf++)
                    mma_tf32(acc[mf][nf], a[mf], b);
            }
        }
        __syncthreads();
    }

    // ---- epilogue: exact store to g_o (each (t,slot) row owned by one expert)
    #pragma unroll
    for (int mf = 0; mf < 2; mf++) {
        #pragma unroll
        for (int half = 0; half < 2; half++) {
            int rl = mw0 + mf * 16 + gid + half * 8;
            int pk = toks[rl];
            if (pk < 0) continue;
            #pragma unroll
            for (int nf = 0; nf < 4; nf++) {
                int col = col0 + nw0 + nf * 8 + 2 * tcol;
                float2 o;
                o.x = acc[mf][nf][half * 2 + 0];
                o.y = acc[mf][nf][half * 2 + 1];
                *(float2*)&g_o[(size_t)pk * H_DIM + col] = o;
            }
        }
    }
}

// -------- reduce: out[t] = sum_s g_o[t*8+s] ---------------------------------
__global__ __launch_bounds__(256) void reduce_kernel(float* __restrict__ out)
{
    int id = blockIdx.x * 256 + threadIdx.x;      // 2048 * 512 threads
    int t  = id >> 9;
    int c4 = (id & 511);
    const float4* base = (const float4*)(g_o + (size_t)t * TOPK * H_DIM) + c4;
    float4 s = base[0];
    #pragma unroll
    for (int sl = 1; sl < TOPK; sl++) {
        float4 v = base[(size_t)sl * (H_DIM / 4)];
        s.x += v.x; s.y += v.y; s.z += v.z; s.w += v.w;
    }
    ((float4*)out)[id] = s;
}

// ---------------------------------------------------------------------------
extern "C" void kernel_launch(void* const* d_in, const int* in_sizes, int n_in,
                              void* d_out, int out_size)
{
    const float* x  = (const float*)d_in[0];   // [1,2048,2048]
    const float* gw = (const float*)d_in[1];   // [32,2048]
    const float* wg = (const float*)d_in[2];   // [32,768,2048]
    const float* wu = (const float*)d_in[3];   // [32,768,2048]
    const float* wd = (const float*)d_in[4];   // [32,2048,768]
    float* out = (float*)d_out;                // [1,2048,2048] f32

    init_kernel<<<1, 32>>>();
    router_kernel<<<T_TOK, 256>>>(x, gw);
    phaseA_kernel<<<dim3(16, I_DIM / 64, N_EXP), 256>>>(x, wg, wu);
    phaseB_kernel<<<dim3(16, H_DIM / 64, N_EXP), 256>>>(wd);
    reduce_kernel<<<(T_TOK * (H_DIM / 4)) / 256, 256>>>(out);
}

// round 3
// speedup vs baseline: 4.4234x; 1.8269x over previous
#include <cuda_runtime.h>
#include <cstdint>
#include <cstddef>

#define T_TOK 2048
#define H_DIM 2048
#define N_EXP 32
#define I_DIM 768
#define TOPK  8
#define PAD   20

// -------- static device scratch --------------------------------------------
__device__ int   g_cnt[N_EXP];
__device__ int   g_list[N_EXP * T_TOK];               // packed token*8+slot
__device__ float g_rw[T_TOK * TOPK];
__device__ float g_h[(size_t)T_TOK * TOPK * I_DIM];   // 50 MB intermediate
__device__ float g_o[(size_t)T_TOK * TOPK * H_DIM];   // 134 MB per-slot down-proj

// -------- helpers -----------------------------------------------------------
__device__ __forceinline__ uint32_t f2tf32(float x) {
    uint32_t r;
    asm("cvt.rna.tf32.f32 %0, %1;" : "=r"(r) : "f"(x));
    return r;
}

__device__ __forceinline__ void mma_tf32(float d[4], const uint32_t a[4], const uint32_t b[2]) {
    asm volatile(
        "mma.sync.aligned.m16n8k8.row.col.f32.tf32.tf32.f32 "
        "{%0,%1,%2,%3},{%4,%5,%6,%7},{%8,%9},{%0,%1,%2,%3};"
        : "+f"(d[0]), "+f"(d[1]), "+f"(d[2]), "+f"(d[3])
        : "r"(a[0]), "r"(a[1]), "r"(a[2]), "r"(a[3]), "r"(b[0]), "r"(b[1]));
}

__device__ __forceinline__ void cp16(uint32_t dst, const void* src, int valid) {
    asm volatile("cp.async.cg.shared.global [%0], [%1], 16, %2;"
                 :: "r"(dst), "l"(src), "r"(valid ? 16 : 0));
}
#define CP_COMMIT() asm volatile("cp.async.commit_group;")
#define CP_WAIT1()  asm volatile("cp.async.wait_group 1;")

// -------- init --------------------------------------------------------------
__global__ void init_kernel()
{
    if (threadIdx.x < N_EXP) g_cnt[threadIdx.x] = 0;
}

// -------- router -------------------------------------------------------------
__global__ __launch_bounds__(256) void router_kernel(
    const float* __restrict__ x, const float* __restrict__ gw)
{
    __shared__ float xs[H_DIM];
    __shared__ float logits[N_EXP];

    const int t = blockIdx.x;
    const float* xr = x + (size_t)t * H_DIM;
    for (int i = threadIdx.x; i < H_DIM; i += 256) xs[i] = xr[i];
    __syncthreads();

    const int warp = threadIdx.x >> 5;
    const int lane = threadIdx.x & 31;

    float acc[4] = {0.f, 0.f, 0.f, 0.f};
    for (int k = lane; k < H_DIM; k += 32) {
        float xv = xs[k];
        #pragma unroll
        for (int q = 0; q < 4; q++)
            acc[q] = fmaf(xv, gw[(size_t)(warp * 4 + q) * H_DIM + k], acc[q]);
    }
    #pragma unroll
    for (int q = 0; q < 4; q++) {
        float v = acc[q];
        #pragma unroll
        for (int off = 16; off; off >>= 1)
            v += __shfl_down_sync(0xffffffffu, v, off);
        if (lane == 0) logits[warp * 4 + q] = v;
    }
    __syncthreads();

    if (threadIdx.x == 0) {
        float lg[N_EXP];
        #pragma unroll
        for (int i = 0; i < N_EXP; i++) lg[i] = logits[i];

        int   sel[TOPK];
        float sv[TOPK];
        #pragma unroll
        for (int s = 0; s < TOPK; s++) {
            int best = 0; float bv = -3.4e38f;
            #pragma unroll
            for (int i = 0; i < N_EXP; i++)
                if (lg[i] > bv) { bv = lg[i]; best = i; }
            sel[s] = best; sv[s] = bv; lg[best] = -3.4e38f;
        }
        float mx = sv[0];
        float ex[TOPK], sum = 0.f;
        #pragma unroll
        for (int s = 0; s < TOPK; s++) { ex[s] = __expf(sv[s] - mx); sum += ex[s]; }
        float inv = 1.f / sum;
        #pragma unroll
        for (int s = 0; s < TOPK; s++) {
            int e = sel[s];
            int pos = atomicAdd(&g_cnt[e], 1);
            g_list[e * T_TOK + pos] = t * TOPK + s;
            g_rw[t * TOPK + s] = ex[s] * inv;
        }
    }
}

// ============================================================================
// phase A: h = silu(x@Wg^T) * (x@Wu^T) * rw
// BM=128, BN=128, BK=16; 8 warps 2Mx4N, warp tile 64x32; A frag shared g/u.
// 3-stage cp.async pipeline. dyn smem = 9*128*PAD*4 = 92160 B
// ============================================================================
__global__ __launch_bounds__(256) void phaseA_kernel(
    const float* __restrict__ x,
    const float* __restrict__ wg,
    const float* __restrict__ wu)
{
    const int e    = blockIdx.z;
    const int cnt  = g_cnt[e];
    const int row0 = blockIdx.x * 128;
    if (row0 >= cnt) return;
    const int col0 = blockIdx.y * 128;

    extern __shared__ float sm[];
    float* Xs = sm;                  // [3][128][PAD]
    float* Gs = sm + 3 * 128 * PAD;
    float* Us = sm + 6 * 128 * PAD;
    __shared__ int toks[128];

    const int tid = threadIdx.x;
    if (tid < 128) {
        int r = row0 + tid;
        toks[tid] = (r < cnt) ? g_list[e * T_TOK + r] : -1;
    }
    __syncthreads();

    const float* wgE = wg + (size_t)e * I_DIM * H_DIM + (size_t)col0 * H_DIM;
    const float* wuE = wu + (size_t)e * I_DIM * H_DIM + (size_t)col0 * H_DIM;

    const int warp  = tid >> 5;
    const int lane  = tid & 31;
    const int warpM = warp & 1;
    const int warpN = warp >> 1;
    const int gid   = lane >> 2;
    const int tcol  = lane & 3;
    const int mw0   = warpM * 64;
    const int nw0   = warpN * 32;

    float accG[4][4][4] = {};
    float accU[4][4][4] = {};

    auto stage = [&](int kt, int buf) {
        const int k0 = kt * 16;
        #pragma unroll
        for (int i = 0; i < 2; i++) {
            int c  = i * 256 + tid;       // 0..511
            int m  = c >> 2;
            int kc = (c & 3) * 4;
            int pk = toks[m];
            const float* xsrc = (pk >= 0)
                ? &x[(size_t)(pk >> 3) * H_DIM + k0 + kc] : x;
            cp16((uint32_t)__cvta_generic_to_shared(&Xs[(buf * 128 + m) * PAD + kc]), xsrc, pk >= 0);
            cp16((uint32_t)__cvta_generic_to_shared(&Gs[(buf * 128 + m) * PAD + kc]),
                 &wgE[(size_t)m * H_DIM + k0 + kc], 1);
            cp16((uint32_t)__cvta_generic_to_shared(&Us[(buf * 128 + m) * PAD + kc]),
                 &wuE[(size_t)m * H_DIM + k0 + kc], 1);
        }
    };

    const int KT = H_DIM / 16;   // 128
    stage(0, 0); CP_COMMIT();
    stage(1, 1); CP_COMMIT();

    for (int kt = 0; kt < KT; kt++) {
        const int buf = kt % 3;
        CP_WAIT1();
        __syncthreads();
        if (kt + 2 < KT) stage(kt + 2, (kt + 2) % 3);
        CP_COMMIT();

        const float* Xb = &Xs[buf * 128 * PAD];
        const float* Gb = &Gs[buf * 128 * PAD];
        const float* Ub = &Us[buf * 128 * PAD];

        #pragma unroll
        for (int ks = 0; ks < 2; ks++) {
            const int kk = ks * 8;
            uint32_t a[4][4];
            #pragma unroll
            for (int mf = 0; mf < 4; mf++) {
                int r = mw0 + mf * 16 + gid;
                a[mf][0] = f2tf32(Xb[r * PAD + kk + tcol]);
                a[mf][1] = f2tf32(Xb[(r + 8) * PAD + kk + tcol]);
                a[mf][2] = f2tf32(Xb[r * PAD + kk + tcol + 4]);
                a[mf][3] = f2tf32(Xb[(r + 8) * PAD + kk + tcol + 4]);
            }
            #pragma unroll
            for (int nf = 0; nf < 4; nf++) {
                int c = nw0 + nf * 8 + gid;
                uint32_t bg[2], bu[2];
                bg[0] = f2tf32(Gb[c * PAD + kk + tcol]);
                bg[1] = f2tf32(Gb[c * PAD + kk + tcol + 4]);
                bu[0] = f2tf32(Ub[c * PAD + kk + tcol]);
                bu[1] = f2tf32(Ub[c * PAD + kk + tcol + 4]);
                #pragma unroll
                for (int mf = 0; mf < 4; mf++) {
                    mma_tf32(accG[mf][nf], a[mf], bg);
                    mma_tf32(accU[mf][nf], a[mf], bu);
                }
            }
        }
    }

    // epilogue
    #pragma unroll
    for (int mf = 0; mf < 4; mf++) {
        #pragma unroll
        for (int half = 0; half < 2; half++) {
            int rl = mw0 + mf * 16 + gid + half * 8;
            int pk = toks[rl];
            if (pk < 0) continue;
            float w = g_rw[pk];
            #pragma unroll
            for (int nf = 0; nf < 4; nf++) {
                int col = col0 + nw0 + nf * 8 + 2 * tcol;
                float g0 = accG[mf][nf][half * 2 + 0];
                float g1 = accG[mf][nf][half * 2 + 1];
                float u0 = accU[mf][nf][half * 2 + 0];
                float u1 = accU[mf][nf][half * 2 + 1];
                float2 o;
                o.x = (g0 / (1.f + __expf(-g0))) * u0 * w;
                o.y = (g1 / (1.f + __expf(-g1))) * u1 * w;
                *(float2*)&g_h[(size_t)pk * I_DIM + col] = o;
            }
        }
    }
}

// ============================================================================
// phase B: g_o[pk] = h[pk] @ Wd[e]^T
// BM=128, BN=128, BK=16; warp tile 64x32; 3-stage cp.async.
// dyn smem = 6*128*PAD*4 = 61440 B
// ============================================================================
__global__ __launch_bounds__(256) void phaseB_kernel(
    const float* __restrict__ wd)
{
    const int e    = blockIdx.z;
    const int cnt  = g_cnt[e];
    const int row0 = blockIdx.x * 128;
    if (row0 >= cnt) return;
    const int col0 = blockIdx.y * 128;

    extern __shared__ float sm[];
    float* Hs = sm;                  // [3][128][PAD]
    float* Ds = sm + 3 * 128 * PAD;
    __shared__ int toks[128];

    const int tid = threadIdx.x;
    if (tid < 128) {
        int r = row0 + tid;
        toks[tid] = (r < cnt) ? g_list[e * T_TOK + r] : -1;
    }
    __syncthreads();

    const float* wdE = wd + (size_t)e * H_DIM * I_DIM + (size_t)col0 * I_DIM;

    const int warp  = tid >> 5;
    const int lane  = tid & 31;
    const int warpM = warp & 1;
    const int warpN = warp >> 1;
    const int gid   = lane >> 2;
    const int tcol  = lane & 3;
    const int mw0   = warpM * 64;
    const int nw0   = warpN * 32;

    float acc[4][4][4] = {};

    auto stage = [&](int kt, int buf) {
        const int k0 = kt * 16;
        #pragma unroll
        for (int i = 0; i < 2; i++) {
            int c  = i * 256 + tid;
            int m  = c >> 2;
            int kc = (c & 3) * 4;
            int pk = toks[m];
            const float* hsrc = (pk >= 0)
                ? &g_h[(size_t)pk * I_DIM + k0 + kc] : g_h;
            cp16((uint32_t)__cvta_generic_to_shared(&Hs[(buf * 128 + m) * PAD + kc]), hsrc, pk >= 0);
            cp16((uint32_t)__cvta_generic_to_shared(&Ds[(buf * 128 + m) * PAD + kc]),
                 &wdE[(size_t)m * I_DIM + k0 + kc], 1);
        }
    };

    const int KT = I_DIM / 16;   // 48
    stage(0, 0); CP_COMMIT();
    stage(1, 1); CP_COMMIT();

    for (int kt = 0; kt < KT; kt++) {
        const int buf = kt % 3;
        CP_WAIT1();
        __syncthreads();
        if (kt + 2 < KT) stage(kt + 2, (kt + 2) % 3);
        CP_COMMIT();

        const float* Hb = &Hs[buf * 128 * PAD];
        const float* Db = &Ds[buf * 128 * PAD];

        #pragma unroll
        for (int ks = 0; ks < 2; ks++) {
            const int kk = ks * 8;
            uint32_t a[4][4];
            #pragma unroll
            for (int mf = 0; mf < 4; mf++) {
                int r = mw0 + mf * 16 + gid;
                a[mf][0] = f2tf32(Hb[r * PAD + kk + tcol]);
                a[mf][1] = f2tf32(Hb[(r + 8) * PAD + kk + tcol]);
                a[mf][2] = f2tf32(Hb[r * PAD + kk + tcol + 4]);
                a[mf][3] = f2tf32(Hb[(r + 8) * PAD + kk + tcol + 4]);
            }
            #pragma unroll
            for (int nf = 0; nf < 4; nf++) {
                int c = nw0 + nf * 8 + gid;
                uint32_t b[2];
                b[0] = f2tf32(Db[c * PAD + kk + tcol]);
                b[1] = f2tf32(Db[c * PAD + kk + tcol + 4]);
                #pragma unroll
                for (int mf = 0; mf < 4; mf++)
                    mma_tf32(acc[mf][nf], a[mf], b);
            }
        }
    }

    // epilogue: exact per-row store (each (t,slot) owned by exactly one expert)
    #pragma unroll
    for (int mf = 0; mf < 4; mf++) {
        #pragma unroll
        for (int half = 0; half < 2; half++) {
            int rl = mw0 + mf * 16 + gid + half * 8;
            int pk = toks[rl];
            if (pk < 0) continue;
            #pragma unroll
            for (int nf = 0; nf < 4; nf++) {
                int col = col0 + nw0 + nf * 8 + 2 * tcol;
                float2 o;
                o.x = acc[mf][nf][half * 2 + 0];
                o.y = acc[mf][nf][half * 2 + 1];
                *(float2*)&g_o[(size_t)pk * H_DIM + col] = o;
            }
        }
    }
}

// -------- reduce: out[t] = sum_s g_o[t*8+s] ---------------------------------
__global__ __launch_bounds__(256) void reduce_kernel(float* __restrict__ out)
{
    int id = blockIdx.x * 256 + threadIdx.x;      // T_TOK * 512 threads
    int t  = id >> 9;
    int c4 = (id & 511);
    const float4* base = (const float4*)(g_o + (size_t)t * TOPK * H_DIM) + c4;
    float4 s = base[0];
    #pragma unroll
    for (int sl = 1; sl < TOPK; sl++) {
        float4 v = base[(size_t)sl * (H_DIM / 4)];
        s.x += v.x; s.y += v.y; s.z += v.z; s.w += v.w;
    }
    ((float4*)out)[id] = s;
}

// ---------------------------------------------------------------------------
extern "C" void kernel_launch(void* const* d_in, const int* in_sizes, int n_in,
                              void* d_out, int out_size)
{
    const float* x  = (const float*)d_in[0];   // [1,2048,2048]
    const float* gw = (const float*)d_in[1];   // [32,2048]
    const float* wg = (const float*)d_in[2];   // [32,768,2048]
    const float* wu = (const float*)d_in[3];   // [32,768,2048]
    const float* wd = (const float*)d_in[4];   // [32,2048,768]
    float* out = (float*)d_out;                // [1,2048,2048] f32

    const int smemA = 9 * 128 * PAD * 4;   // 92160
    const int smemB = 6 * 128 * PAD * 4;   // 61440
    static bool attr_done = false;
    if (!attr_done) {
        cudaFuncSetAttribute(phaseA_kernel, cudaFuncAttributeMaxDynamicSharedMemorySize, smemA);
        cudaFuncSetAttribute(phaseB_kernel, cudaFuncAttributeMaxDynamicSharedMemorySize, smemB);
        attr_done = true;
    }

    init_kernel<<<1, 32>>>();
    router_kernel<<<T_TOK, 256>>>(x, gw);
    phaseA_kernel<<<dim3(16, I_DIM / 128, N_EXP), 256, smemA>>>(x, wg, wu);
    phaseB_kernel<<<dim3(16, H_DIM / 128, N_EXP), 256, smemB>>>(wd);
    reduce_kernel<<<(T_TOK * (H_DIM / 4)) / 256, 256>>>(out);
}

// round 5
// speedup vs baseline: 4.8146x; 1.0884x over previous
#include <cuda_runtime.h>
#include <cstdint>
#include <cstddef>

#define T_TOK 2048
#define H_DIM 2048
#define N_EXP 32
#define I_DIM 768
#define TOPK  8
#define ROWB  192   // smem row pitch in bytes (48 floats)

// -------- static device scratch --------------------------------------------
__device__ int   g_cnt[N_EXP];
__device__ int   g_list[N_EXP * T_TOK];
__device__ float g_rw[T_TOK * TOPK];
__device__ float g_xp[(size_t)T_TOK * H_DIM];          // 16 MB x, permuted+tf32
__device__ float g_h[(size_t)T_TOK * TOPK * I_DIM];    // 50 MB, permuted+tf32
__device__ float g_o[(size_t)T_TOK * TOPK * H_DIM];    // 134 MB fp32

// -------- helpers -----------------------------------------------------------
__device__ __forceinline__ uint32_t f2tf32(float x) {
    uint32_t r; asm("cvt.rna.tf32.f32 %0, %1;" : "=r"(r) : "f"(x)); return r;
}
__device__ __forceinline__ uint32_t sptr(const void* p) {
    return (uint32_t)__cvta_generic_to_shared(p);
}
__device__ __forceinline__ void sts32(uint32_t a, uint32_t v) {
    asm volatile("st.shared.b32 [%0], %1;" :: "r"(a), "r"(v));
}
__device__ __forceinline__ uint4 lds128(uint32_t a) {
    uint4 v;
    asm volatile("ld.shared.v4.b32 {%0,%1,%2,%3}, [%4];"
                 : "=r"(v.x), "=r"(v.y), "=r"(v.z), "=r"(v.w) : "r"(a));
    return v;
}
__device__ __forceinline__ void cp16(uint32_t dst, const void* src, int valid) {
    asm volatile("cp.async.cg.shared.global [%0], [%1], 16, %2;"
                 :: "r"(dst), "l"(src), "r"(valid ? 16 : 0));
}
#define CP_COMMIT() asm volatile("cp.async.commit_group;")
#define CP_WAIT0()  asm volatile("cp.async.wait_group 0;")

__device__ __forceinline__ void mma_tf32(float* d, uint32_t a0, uint32_t a1,
                                         uint32_t a2, uint32_t a3,
                                         uint32_t b0, uint32_t b1) {
    asm volatile(
        "mma.sync.aligned.m16n8k8.row.col.f32.tf32.tf32.f32 "
        "{%0,%1,%2,%3},{%4,%5,%6,%7},{%8,%9},{%0,%1,%2,%3};"
        : "+f"(d[0]), "+f"(d[1]), "+f"(d[2]), "+f"(d[3])
        : "r"(a0), "r"(a1), "r"(a2), "r"(a3), "r"(b0), "r"(b1));
}

// permuted index of k within its 16-group: pos = 4*(k%4) + k/4
__device__ __forceinline__ int kperm(int k) {
    return (k & ~15) + 4 * (k & 3) + ((k & 15) >> 2);
}

// -------- init ---------------------------------------------------------------
__global__ void init_kernel() { if (threadIdx.x < N_EXP) g_cnt[threadIdx.x] = 0; }

// -------- x -> permuted tf32 copy ---------------------------------------------
__global__ __launch_bounds__(256) void xperm_kernel(const float* __restrict__ x)
{
    int q = blockIdx.x * 256 + threadIdx.x;       // quad id over T*H/4
    int row = q >> 9;                             // H/4 = 512 quads per row
    int kc4 = q & 511;
    float4 v = ((const float4*)x)[q];
    float* dst = g_xp + (size_t)row * H_DIM;
    int grp = (kc4 >> 2) * 16;
    int c   = kc4 & 3;
    dst[grp + c + 0]  = __uint_as_float(f2tf32(v.x));
    dst[grp + c + 4]  = __uint_as_float(f2tf32(v.y));
    dst[grp + c + 8]  = __uint_as_float(f2tf32(v.z));
    dst[grp + c + 12] = __uint_as_float(f2tf32(v.w));
}

// -------- router ---------------------------------------------------------------
__global__ __launch_bounds__(256) void router_kernel(
    const float* __restrict__ x, const float* __restrict__ gw)
{
    __shared__ float xs[H_DIM];
    __shared__ float logits[N_EXP];

    const int t = blockIdx.x;
    const float* xr = x + (size_t)t * H_DIM;
    for (int i = threadIdx.x; i < H_DIM; i += 256) xs[i] = xr[i];
    __syncthreads();

    const int warp = threadIdx.x >> 5;
    const int lane = threadIdx.x & 31;

    float acc[4] = {0.f, 0.f, 0.f, 0.f};
    for (int k = lane; k < H_DIM; k += 32) {
        float xv = xs[k];
        #pragma unroll
        for (int q = 0; q < 4; q++)
            acc[q] = fmaf(xv, gw[(size_t)(warp * 4 + q) * H_DIM + k], acc[q]);
    }
    #pragma unroll
    for (int q = 0; q < 4; q++) {
        float v = acc[q];
        #pragma unroll
        for (int off = 16; off; off >>= 1)
            v += __shfl_down_sync(0xffffffffu, v, off);
        if (lane == 0) logits[warp * 4 + q] = v;
    }
    __syncthreads();

    if (threadIdx.x == 0) {
        float lg[N_EXP];
        #pragma unroll
        for (int i = 0; i < N_EXP; i++) lg[i] = logits[i];
        int   sel[TOPK];
        float sv[TOPK];
        #pragma unroll
        for (int s = 0; s < TOPK; s++) {
            int best = 0; float bv = -3.4e38f;
            #pragma unroll
            for (int i = 0; i < N_EXP; i++)
                if (lg[i] > bv) { bv = lg[i]; best = i; }
            sel[s] = best; sv[s] = bv; lg[best] = -3.4e38f;
        }
        float mx = sv[0];
        float ex[TOPK], sum = 0.f;
        #pragma unroll
        for (int s = 0; s < TOPK; s++) { ex[s] = __expf(sv[s] - mx); sum += ex[s]; }
        float inv = 1.f / sum;
        #pragma unroll
        for (int s = 0; s < TOPK; s++) {
            int e = sel[s];
            int pos = atomicAdd(&g_cnt[e], 1);
            g_list[e * T_TOK + pos] = t * TOPK + s;
            g_rw[t * TOPK + s] = ex[s] * inv;
        }
    }
}

// ============================================================================
// phase A: h = silu(x@Wg^T)*(x@Wu^T)*rw
// BM=128, BN=64, BK=32. 8 warps = 2M x 4N, warp tile 64x16, 2 tensors.
// A via cp.async (g_xp, permuted tf32); Wg/Wu via LDG->cvt->STS reg pipeline.
// smem/stage: A 128*192 + G 64*192 + U 64*192 = 49152; x2 = 98304
// ============================================================================
__global__ __launch_bounds__(256, 2) void phaseA_kernel(
    const float* __restrict__ wg, const float* __restrict__ wu)
{
    const int e    = blockIdx.z;
    const int cnt  = g_cnt[e];
    const int row0 = blockIdx.x * 128;
    if (row0 >= cnt) return;
    const int col0 = blockIdx.y * 64;

    extern __shared__ __align__(16) float dsm[];
    __shared__ int toks[128];

    const uint32_t S   = sptr(dsm);
    const uint32_t AS  = S;               // 24576 per stage
    const uint32_t GS  = S + 24576;       // 12288
    const uint32_t US  = S + 36864;       // 12288
    const uint32_t STG = 49152;

    const int tid = threadIdx.x;
    if (tid < 128) {
        int r = row0 + tid;
        toks[tid] = (r < cnt) ? g_list[e * T_TOK + r] : -1;
    }
    __syncthreads();

    const float* wgE = wg + (size_t)e * I_DIM * H_DIM + (size_t)col0 * H_DIM;
    const float* wuE = wu + (size_t)e * I_DIM * H_DIM + (size_t)col0 * H_DIM;

    const int warp = tid >> 5, lane = tid & 31;
    const int gid  = lane >> 2, tcol = lane & 3;
    const int mw0  = (warp & 1) * 64;
    const int nw0  = (warp >> 1) * 16;

    float accG[4][2][4] = {};
    float accU[4][2][4] = {};
    float4 gq[2], uq[2];

    // A-tile cp.async gather for step kt into stage buffer
    auto ldgA = [&](int kt, int buf) {
        const int k0 = kt * 32;
        #pragma unroll
        for (int j = 0; j < 4; j++) {
            int qid = j * 256 + tid;              // 1024 quads
            int r   = qid >> 3;
            int kc4 = qid & 7;
            int pk  = toks[r];
            const float* src = (pk >= 0)
                ? &g_xp[(size_t)(pk >> 3) * H_DIM + k0 + kc4 * 4] : g_xp;
            cp16(AS + buf * STG + r * ROWB + (kc4 >> 2) * 64 + (kc4 & 3) * 16,
                 src, pk >= 0);
        }
    };
    // weight LDG for step kt into regs
    auto ldgW = [&](int kt) {
        const int k0 = kt * 32;
        #pragma unroll
        for (int j = 0; j < 2; j++) {
            int qid = j * 256 + tid;              // 512 quads per tensor
            int r   = qid >> 3;
            int kc4 = qid & 7;
            gq[j] = *(const float4*)&wgE[(size_t)r * H_DIM + k0 + kc4 * 4];
            uq[j] = *(const float4*)&wuE[(size_t)r * H_DIM + k0 + kc4 * 4];
        }
    };
    // cvt + permuted STS of staged weights
    auto stsW = [&](int buf) {
        #pragma unroll
        for (int j = 0; j < 2; j++) {
            int qid = j * 256 + tid;
            int r   = qid >> 3;
            int kc4 = qid & 7;
            uint32_t bG = GS + buf * STG + r * ROWB + (kc4 >> 2) * 64 + (kc4 & 3) * 4;
            sts32(bG +  0, f2tf32(gq[j].x));
            sts32(bG + 16, f2tf32(gq[j].y));
            sts32(bG + 32, f2tf32(gq[j].z));
            sts32(bG + 48, f2tf32(gq[j].w));
            uint32_t bU = US + buf * STG + r * ROWB + (kc4 >> 2) * 64 + (kc4 & 3) * 4;
            sts32(bU +  0, f2tf32(uq[j].x));
            sts32(bU + 16, f2tf32(uq[j].y));
            sts32(bU + 32, f2tf32(uq[j].z));
            sts32(bU + 48, f2tf32(uq[j].w));
        }
    };

    const int KT = H_DIM / 32;   // 64
    ldgA(0, 0); CP_COMMIT();
    ldgW(0);

    for (int kt = 0; kt < KT; kt++) {
        const int buf = kt & 1;
        stsW(buf);
        CP_WAIT0();
        __syncthreads();
        if (kt + 1 < KT) {
            ldgA(kt + 1, buf ^ 1); CP_COMMIT();
            ldgW(kt + 1);
        }

        const uint32_t Ab = AS + buf * STG;
        const uint32_t Gb = GS + buf * STG;
        const uint32_t Ub = US + buf * STG;

        #pragma unroll
        for (int grp = 0; grp < 2; grp++) {
            uint4 BG[2], BU[2];
            #pragma unroll
            for (int nf = 0; nf < 2; nf++) {
                int c = nw0 + nf * 8 + gid;
                BG[nf] = lds128(Gb + c * ROWB + grp * 64 + tcol * 16);
                BU[nf] = lds128(Ub + c * ROWB + grp * 64 + tcol * 16);
            }
            #pragma unroll
            for (int mf = 0; mf < 4; mf++) {
                int r = mw0 + mf * 16 + gid;
                uint4 A0 = lds128(Ab + r * ROWB + grp * 64 + tcol * 16);
                uint4 A1 = lds128(Ab + (r + 8) * ROWB + grp * 64 + tcol * 16);
                // ks = 0
                mma_tf32(accG[mf][0], A0.x, A1.x, A0.y, A1.y, BG[0].x, BG[0].y);
                mma_tf32(accG[mf][1], A0.x, A1.x, A0.y, A1.y, BG[1].x, BG[1].y);
                mma_tf32(accU[mf][0], A0.x, A1.x, A0.y, A1.y, BU[0].x, BU[0].y);
                mma_tf32(accU[mf][1], A0.x, A1.x, A0.y, A1.y, BU[1].x, BU[1].y);
                // ks = 1
                mma_tf32(accG[mf][0], A0.z, A1.z, A0.w, A1.w, BG[0].z, BG[0].w);
                mma_tf32(accG[mf][1], A0.z, A1.z, A0.w, A1.w, BG[1].z, BG[1].w);
                mma_tf32(accU[mf][0], A0.z, A1.z, A0.w, A1.w, BU[0].z, BU[0].w);
                mma_tf32(accU[mf][1], A0.z, A1.z, A0.w, A1.w, BU[1].z, BU[1].w);
            }
        }
    }

    // epilogue: silu(g)*u*rw, tf32-rounded, permuted store to g_h
    #pragma unroll
    for (int mf = 0; mf < 4; mf++) {
        #pragma unroll
        for (int half = 0; half < 2; half++) {
            int rl = mw0 + mf * 16 + gid + half * 8;
            int pk = toks[rl];
            if (pk < 0) continue;
            float w = g_rw[pk];
            float* hrow = g_h + (size_t)pk * I_DIM;
            #pragma unroll
            for (int nf = 0; nf < 2; nf++) {
                #pragma unroll
                for (int ee = 0; ee < 2; ee++) {
                    int c = col0 + nw0 + nf * 8 + 2 * tcol + ee;
                    float g = accG[mf][nf][half * 2 + ee];
                    float u = accU[mf][nf][half * 2 + ee];
                    float h = (g / (1.f + __expf(-g))) * u * w;
                    hrow[kperm(c)] = __uint_as_float(f2tf32(h));
                }
            }
        }
    }
}

// ============================================================================
// phase B: g_o[pk] = h[pk] @ Wd^T
// BM=128, BN=128, BK=32. 8 warps = 2M x 4N, warp tile 64x32.
// H via cp.async (permuted tf32); Wd via LDG->cvt->STS reg pipeline.
// smem/stage: H 128*192 + D 128*192 = 49152; x2 = 98304
// ============================================================================
__global__ __launch_bounds__(256, 2) void phaseB_kernel(
    const float* __restrict__ wd)
{
    const int e    = blockIdx.z;
    const int cnt  = g_cnt[e];
    const int row0 = blockIdx.x * 128;
    if (row0 >= cnt) return;
    const int col0 = blockIdx.y * 128;

    extern __shared__ __align__(16) float dsm[];
    __shared__ int toks[128];

    const uint32_t S   = sptr(dsm);
    const uint32_t HS  = S;               // 24576
    const uint32_t DS  = S + 24576;       // 24576
    const uint32_t STG = 49152;

    const int tid = threadIdx.x;
    if (tid < 128) {
        int r = row0 + tid;
        toks[tid] = (r < cnt) ? g_list[e * T_TOK + r] : -1;
    }
    __syncthreads();

    const float* wdE = wd + (size_t)e * H_DIM * I_DIM + (size_t)col0 * I_DIM;

    const int warp = tid >> 5, lane = tid & 31;
    const int gid  = lane >> 2, tcol = lane & 3;
    const int mw0  = (warp & 1) * 64;
    const int nw0  = (warp >> 1) * 32;

    float acc[4][4][4] = {};
    float4 dq[4];

    auto ldgH = [&](int kt, int buf) {
        const int k0 = kt * 32;
        #pragma unroll
        for (int j = 0; j < 4; j++) {
            int qid = j * 256 + tid;
            int r   = qid >> 3;
            int kc4 = qid & 7;
            int pk  = toks[r];
            const float* src = (pk >= 0)
                ? &g_h[(size_t)pk * I_DIM + k0 + kc4 * 4] : g_h;
            cp16(HS + buf * STG + r * ROWB + (kc4 >> 2) * 64 + (kc4 & 3) * 16,
                 src, pk >= 0);
        }
    };
    auto ldgW = [&](int kt) {
        const int k0 = kt * 32;
        #pragma unroll
        for (int j = 0; j < 4; j++) {
            int qid = j * 256 + tid;
            int r   = qid >> 3;
            int kc4 = qid & 7;
            dq[j] = *(const float4*)&wdE[(size_t)r * I_DIM + k0 + kc4 * 4];
        }
    };
    auto stsW = [&](int buf) {
        #pragma unroll
        for (int j = 0; j < 4; j++) {
            int qid = j * 256 + tid;
            int r   = qid >> 3;
            int kc4 = qid & 7;
            uint32_t b = DS + buf * STG + r * ROWB + (kc4 >> 2) * 64 + (kc4 & 3) * 4;
            sts32(b +  0, f2tf32(dq[j].x));
            sts32(b + 16, f2tf32(dq[j].y));
            sts32(b + 32, f2tf32(dq[j].z));
            sts32(b + 48, f2tf32(dq[j].w));
        }
    };

    const int KT = I_DIM / 32;   // 24
    ldgH(0, 0); CP_COMMIT();
    ldgW(0);

    for (int kt = 0; kt < KT; kt++) {
        const int buf = kt & 1;
        stsW(buf);
        CP_WAIT0();
        __syncthreads();
        if (kt + 1 < KT) {
            ldgH(kt + 1, buf ^ 1); CP_COMMIT();
            ldgW(kt + 1);
        }

        const uint32_t Hb = HS + buf * STG;
        const uint32_t Db = DS + buf * STG;

        #pragma unroll
        for (int grp = 0; grp < 2; grp++) {
            uint4 BD[4];
            #pragma unroll
            for (int nf = 0; nf < 4; nf++) {
                int c = nw0 + nf * 8 + gid;
                BD[nf] = lds128(Db + c * ROWB + grp * 64 + tcol * 16);
            }
            #pragma unroll
            for (int mf = 0; mf < 4; mf++) {
                int r = mw0 + mf * 16 + gid;
                uint4 A0 = lds128(Hb + r * ROWB + grp * 64 + tcol * 16);
                uint4 A1 = lds128(Hb + (r + 8) * ROWB + grp * 64 + tcol * 16);
                #pragma unroll
                for (int nf = 0; nf < 4; nf++) {
                    mma_tf32(acc[mf][nf], A0.x, A1.x, A0.y, A1.y, BD[nf].x, BD[nf].y);
                    mma_tf32(acc[mf][nf], A0.z, A1.z, A0.w, A1.w, BD[nf].z, BD[nf].w);
                }
            }
        }
    }

    // epilogue: exact per-row store (each (t,slot) owned by one expert)
    #pragma unroll
    for (int mf = 0; mf < 4; mf++) {
        #pragma unroll
        for (int half = 0; half < 2; half++) {
            int rl = mw0 + mf * 16 + gid + half * 8;
            int pk = toks[rl];
            if (pk < 0) continue;
            #pragma unroll
            for (int nf = 0; nf < 4; nf++) {
                int c = col0 + nw0 + nf * 8 + 2 * tcol;
                float2 o;
                o.x = acc[mf][nf][half * 2 + 0];
                o.y = acc[mf][nf][half * 2 + 1];
                *(float2*)&g_o[(size_t)pk * H_DIM + c] = o;
            }
        }
    }
}

// -------- reduce: out[t] = sum_s g_o[t*8+s] ----------------------------------
__global__ __launch_bounds__(256) void reduce_kernel(float* __restrict__ out)
{
    int id = blockIdx.x * 256 + threadIdx.x;
    int t  = id >> 9;
    int c4 = id & 511;
    const float4* b = (const float4*)(g_o + (size_t)t * TOPK * H_DIM) + c4;
    float4 s = b[0];
    #pragma unroll
    for (int sl = 1; sl < TOPK; sl++) {
        float4 v = b[(size_t)sl * (H_DIM / 4)];
        s.x += v.x; s.y += v.y; s.z += v.z; s.w += v.w;
    }
    ((float4*)out)[id] = s;
}

// ---------------------------------------------------------------------------
extern "C" void kernel_launch(void* const* d_in, const int* in_sizes, int n_in,
                              void* d_out, int out_size)
{
    const float* x  = (const float*)d_in[0];
    const float* gw = (const float*)d_in[1];
    const float* wg = (const float*)d_in[2];
    const float* wu = (const float*)d_in[3];
    const float* wd = (const float*)d_in[4];
    float* out = (float*)d_out;

    const int smemAB = 2 * 49152;   // 98304 B
    static bool attr_done = false;
    if (!attr_done) {
        cudaFuncSetAttribute(phaseA_kernel, cudaFuncAttributeMaxDynamicSharedMemorySize, smemAB);
        cudaFuncSetAttribute(phaseB_kernel, cudaFuncAttributeMaxDynamicSharedMemorySize, smemAB);
        attr_done = true;
    }

    init_kernel<<<1, 32>>>();
    xperm_kernel<<<(T_TOK * (H_DIM / 4)) / 256, 256>>>(x);
    router_kernel<<<T_TOK, 256>>>(x, gw);
    phaseA_kernel<<<dim3(16, I_DIM / 64, N_EXP), 256, smemAB>>>(wg, wu);
    phaseB_kernel<<<dim3(16, H_DIM / 128, N_EXP), 256, smemAB>>>(wd);
    reduce_kernel<<<(T_TOK * (H_DIM / 4)) / 256, 256>>>(out);
}

// round 6
// speedup vs baseline: 8.8928x; 1.8471x over previous
#include <cuda_runtime.h>
#include <cuda_fp16.h>
#include <cstdint>
#include <cstddef>

#define T_TOK 2048
#define H_DIM 2048
#define N_EXP 32
#define I_DIM 768
#define TOPK  8
#define PITCH 80        // smem row pitch bytes (32 halves + 16B skew)

// -------- static device scratch --------------------------------------------
__device__ int   g_cnt[N_EXP];
__device__ int   g_list[N_EXP * T_TOK];
__device__ float g_rw[T_TOK * TOPK];
__device__ __align__(16) __half g_xh[(size_t)T_TOK * H_DIM];        // 8 MB  x fp16
__device__ __align__(16) __half g_h[(size_t)T_TOK * TOPK * I_DIM];  // 25 MB h fp16
__device__ float g_o[(size_t)T_TOK * TOPK * H_DIM];                 // 134 MB fp32

// -------- helpers -----------------------------------------------------------
__device__ __forceinline__ uint32_t sptr(const void* p) {
    return (uint32_t)__cvta_generic_to_shared(p);
}
__device__ __forceinline__ uint32_t pk2(float a, float b) {
    __half2 h = __floats2half2_rn(a, b);
    return *(uint32_t*)&h;
}
__device__ __forceinline__ void sts128(uint32_t a, uint32_t x0, uint32_t x1,
                                       uint32_t x2, uint32_t x3) {
    asm volatile("st.shared.v4.b32 [%0], {%1,%2,%3,%4};"
                 :: "r"(a), "r"(x0), "r"(x1), "r"(x2), "r"(x3));
}
__device__ __forceinline__ void cp16(uint32_t dst, const void* src, int valid) {
    asm volatile("cp.async.cg.shared.global [%0], [%1], 16, %2;"
                 :: "r"(dst), "l"(src), "r"(valid ? 16 : 0));
}
#define CP_COMMIT() asm volatile("cp.async.commit_group;")
#define CP_WAIT0()  asm volatile("cp.async.wait_group 0;")

__device__ __forceinline__ void ldsm4(uint32_t* r, uint32_t a) {
    asm volatile("ldmatrix.sync.aligned.m8n8.x4.shared.b16 {%0,%1,%2,%3}, [%4];"
                 : "=r"(r[0]), "=r"(r[1]), "=r"(r[2]), "=r"(r[3]) : "r"(a));
}
__device__ __forceinline__ void ldsm2(uint32_t* r, uint32_t a) {
    asm volatile("ldmatrix.sync.aligned.m8n8.x2.shared.b16 {%0,%1}, [%2];"
                 : "=r"(r[0]), "=r"(r[1]) : "r"(a));
}
__device__ __forceinline__ void mma16(float* d, const uint32_t* a, const uint32_t* b) {
    asm volatile(
        "mma.sync.aligned.m16n8k16.row.col.f32.f16.f16.f32 "
        "{%0,%1,%2,%3},{%4,%5,%6,%7},{%8,%9},{%0,%1,%2,%3};"
        : "+f"(d[0]), "+f"(d[1]), "+f"(d[2]), "+f"(d[3])
        : "r"(a[0]), "r"(a[1]), "r"(a[2]), "r"(a[3]), "r"(b[0]), "r"(b[1]));
}

// -------- init ---------------------------------------------------------------
__global__ void init_kernel() { if (threadIdx.x < N_EXP) g_cnt[threadIdx.x] = 0; }

// -------- x -> fp16 copy -------------------------------------------------------
__global__ __launch_bounds__(256) void xh_kernel(const float* __restrict__ x)
{
    int i = blockIdx.x * 256 + threadIdx.x;          // 8 values per thread
    const float4* s = (const float4*)x + (size_t)i * 2;
    float4 v0 = s[0], v1 = s[1];
    uint4 o;
    o.x = pk2(v0.x, v0.y); o.y = pk2(v0.z, v0.w);
    o.z = pk2(v1.x, v1.y); o.w = pk2(v1.z, v1.w);
    *(uint4*)&g_xh[(size_t)i * 8] = o;
}

// -------- router ---------------------------------------------------------------
__global__ __launch_bounds__(256) void router_kernel(
    const float* __restrict__ x, const float* __restrict__ gw)
{
    __shared__ float xs[H_DIM];
    __shared__ float logits[N_EXP];

    const int t = blockIdx.x;
    const float* xr = x + (size_t)t * H_DIM;
    for (int i = threadIdx.x; i < H_DIM; i += 256) xs[i] = xr[i];
    __syncthreads();

    const int warp = threadIdx.x >> 5;
    const int lane = threadIdx.x & 31;

    float acc[4] = {0.f, 0.f, 0.f, 0.f};
    for (int k = lane; k < H_DIM; k += 32) {
        float xv = xs[k];
        #pragma unroll
        for (int q = 0; q < 4; q++)
            acc[q] = fmaf(xv, gw[(size_t)(warp * 4 + q) * H_DIM + k], acc[q]);
    }
    #pragma unroll
    for (int q = 0; q < 4; q++) {
        float v = acc[q];
        #pragma unroll
        for (int off = 16; off; off >>= 1)
            v += __shfl_down_sync(0xffffffffu, v, off);
        if (lane == 0) logits[warp * 4 + q] = v;
    }
    __syncthreads();

    if (threadIdx.x == 0) {
        float lg[N_EXP];
        #pragma unroll
        for (int i = 0; i < N_EXP; i++) lg[i] = logits[i];
        int   sel[TOPK];
        float sv[TOPK];
        #pragma unroll
        for (int s = 0; s < TOPK; s++) {
            int best = 0; float bv = -3.4e38f;
            #pragma unroll
            for (int i = 0; i < N_EXP; i++)
                if (lg[i] > bv) { bv = lg[i]; best = i; }
            sel[s] = best; sv[s] = bv; lg[best] = -3.4e38f;
        }
        float mx = sv[0];
        float ex[TOPK], sum = 0.f;
        #pragma unroll
        for (int s = 0; s < TOPK; s++) { ex[s] = __expf(sv[s] - mx); sum += ex[s]; }
        float inv = 1.f / sum;
        #pragma unroll
        for (int s = 0; s < TOPK; s++) {
            int e = sel[s];
            int pos = atomicAdd(&g_cnt[e], 1);
            g_list[e * T_TOK + pos] = t * TOPK + s;
            g_rw[t * TOPK + s] = ex[s] * inv;
        }
    }
}

// ============================================================================
// phase A: h = silu(x@Wg^T)*(x@Wu^T)*rw     fp16 MMA m16n8k16, fp32 accum
// BM=128, BN=64, BK=32; 8 warps 2M x 4N; warp tile 64x16 per tensor.
// A via cp.async(g_xh); Wg/Wu via LDG->cvt.f16x2->STS.128 reg pipeline.
// stage = A 10240 + G 5120 + U 5120 = 20480 B; x2 = 40960 B
// ============================================================================
__global__ __launch_bounds__(256, 2) void phaseA_kernel(
    const float* __restrict__ wg, const float* __restrict__ wu)
{
    const int e    = blockIdx.z;
    const int cnt  = g_cnt[e];
    const int row0 = blockIdx.x * 128;
    if (row0 >= cnt) return;
    const int col0 = blockIdx.y * 64;

    extern __shared__ __align__(16) char dsm[];
    __shared__ int toks[128];

    const uint32_t S   = sptr(dsm);
    const uint32_t A0  = S;
    const uint32_t G0  = S + 10240;
    const uint32_t U0  = S + 15360;
    const uint32_t STG = 20480;

    const int tid = threadIdx.x;
    if (tid < 128) {
        int r = row0 + tid;
        toks[tid] = (r < cnt) ? g_list[e * T_TOK + r] : -1;
    }
    __syncthreads();

    const float* wgE = wg + (size_t)e * I_DIM * H_DIM + (size_t)col0 * H_DIM;
    const float* wuE = wu + (size_t)e * I_DIM * H_DIM + (size_t)col0 * H_DIM;

    const int warp = tid >> 5, lane = tid & 31;
    const int gid  = lane >> 2, tcol = lane & 3;
    const int mw0  = (warp & 1) * 64;
    const int nw0  = (warp >> 1) * 16;

    // ldmatrix per-lane offsets
    const uint32_t aoff = (uint32_t)(mw0 + (lane & 15)) * PITCH + ((lane >> 4) * 16);
    const uint32_t boff = (uint32_t)(nw0 + (lane & 7)) * PITCH + (((lane >> 3) & 1) * 16);

    float accG[4][2][4] = {};
    float accU[4][2][4] = {};
    float4 gq[2], uq[2];

    const int wr = tid >> 2;        // weight row 0..63
    const int wc = tid & 3;         // 16B chunk 0..3

    auto ldgA = [&](int kt, int buf) {
        const int k0 = kt * 32;
        #pragma unroll
        for (int j = 0; j < 2; j++) {
            int idx = j * 256 + tid;          // 512 chunks
            int r   = idx >> 2;
            int ch  = idx & 3;
            int pkk = toks[r];
            const __half* src = (pkk >= 0)
                ? &g_xh[(size_t)(pkk >> 3) * H_DIM + k0 + ch * 8] : g_xh;
            cp16(A0 + buf * STG + r * PITCH + ch * 16, src, pkk >= 0);
        }
    };
    auto ldgW = [&](int kt) {
        const int k0 = kt * 32;
        const float* sg = &wgE[(size_t)wr * H_DIM + k0 + wc * 8];
        const float* su = &wuE[(size_t)wr * H_DIM + k0 + wc * 8];
        gq[0] = *(const float4*)sg; gq[1] = *(const float4*)(sg + 4);
        uq[0] = *(const float4*)su; uq[1] = *(const float4*)(su + 4);
    };
    auto stsW = [&](int buf) {
        uint32_t a = G0 + buf * STG + wr * PITCH + wc * 16;
        sts128(a, pk2(gq[0].x, gq[0].y), pk2(gq[0].z, gq[0].w),
                  pk2(gq[1].x, gq[1].y), pk2(gq[1].z, gq[1].w));
        uint32_t b = U0 + buf * STG + wr * PITCH + wc * 16;
        sts128(b, pk2(uq[0].x, uq[0].y), pk2(uq[0].z, uq[0].w),
                  pk2(uq[1].x, uq[1].y), pk2(uq[1].z, uq[1].w));
    };

    const int KT = H_DIM / 32;   // 64
    ldgA(0, 0); CP_COMMIT();
    ldgW(0);

    for (int kt = 0; kt < KT; kt++) {
        const int buf = kt & 1;
        stsW(buf);
        CP_WAIT0();
        __syncthreads();
        if (kt + 1 < KT) {
            ldgA(kt + 1, buf ^ 1); CP_COMMIT();
            ldgW(kt + 1);
        }

        const uint32_t Ab = A0 + buf * STG + aoff;
        const uint32_t Gb = G0 + buf * STG + boff;
        const uint32_t Ub = U0 + buf * STG + boff;

        #pragma unroll
        for (int kc = 0; kc < 2; kc++) {
            const uint32_t kb = kc * 32;
            uint32_t a[4][4];
            #pragma unroll
            for (int mf = 0; mf < 4; mf++) ldsm4(a[mf], Ab + mf * 16 * PITCH + kb);
            uint32_t bg[2][2], bu[2][2];
            #pragma unroll
            for (int nf = 0; nf < 2; nf++) {
                ldsm2(bg[nf], Gb + nf * 8 * PITCH + kb);
                ldsm2(bu[nf], Ub + nf * 8 * PITCH + kb);
            }
            #pragma unroll
            for (int mf = 0; mf < 4; mf++)
                #pragma unroll
                for (int nf = 0; nf < 2; nf++) {
                    mma16(accG[mf][nf], a[mf], bg[nf]);
                    mma16(accU[mf][nf], a[mf], bu[nf]);
                }
        }
    }

    // epilogue: silu(g)*u*rw -> g_h (fp16)
    #pragma unroll
    for (int mf = 0; mf < 4; mf++) {
        #pragma unroll
        for (int half = 0; half < 2; half++) {
            int rl = mw0 + mf * 16 + gid + half * 8;
            int pkk = toks[rl];
            if (pkk < 0) continue;
            float w = g_rw[pkk];
            #pragma unroll
            for (int nf = 0; nf < 2; nf++) {
                int c = col0 + nw0 + nf * 8 + 2 * tcol;
                float g0 = accG[mf][nf][half * 2 + 0];
                float g1 = accG[mf][nf][half * 2 + 1];
                float u0 = accU[mf][nf][half * 2 + 0];
                float u1 = accU[mf][nf][half * 2 + 1];
                float h0 = (g0 / (1.f + __expf(-g0))) * u0 * w;
                float h1 = (g1 / (1.f + __expf(-g1))) * u1 * w;
                *(uint32_t*)&g_h[(size_t)pkk * I_DIM + c] = pk2(h0, h1);
            }
        }
    }
}

// ============================================================================
// phase B: g_o[pk] = h[pk] @ Wd^T    fp16 MMA, fp32 accum
// BM=128, BN=128, BK=32; 8 warps 2M x 4N; warp tile 64x32.
// stage = H 10240 + D 10240 = 20480 B; x2 = 40960 B
// ============================================================================
__global__ __launch_bounds__(256, 2) void phaseB_kernel(
    const float* __restrict__ wd)
{
    const int e    = blockIdx.z;
    const int cnt  = g_cnt[e];
    const int row0 = blockIdx.x * 128;
    if (row0 >= cnt) return;
    const int col0 = blockIdx.y * 128;

    extern __shared__ __align__(16) char dsm[];
    __shared__ int toks[128];

    const uint32_t S   = sptr(dsm);
    const uint32_t H0  = S;
    const uint32_t D0  = S + 10240;
    const uint32_t STG = 20480;

    const int tid = threadIdx.x;
    if (tid < 128) {
        int r = row0 + tid;
        toks[tid] = (r < cnt) ? g_list[e * T_TOK + r] : -1;
    }
    __syncthreads();

    const float* wdE = wd + (size_t)e * H_DIM * I_DIM + (size_t)col0 * I_DIM;

    const int warp = tid >> 5, lane = tid & 31;
    const int gid  = lane >> 2, tcol = lane & 3;
    const int mw0  = (warp & 1) * 64;
    const int nw0  = (warp >> 1) * 32;

    const uint32_t aoff = (uint32_t)(mw0 + (lane & 15)) * PITCH + ((lane >> 4) * 16);
    const uint32_t boff = (uint32_t)(nw0 + (lane & 7)) * PITCH + (((lane >> 3) & 1) * 16);

    float acc[4][4][4] = {};
    float4 dq[4];

    auto ldgH = [&](int kt, int buf) {
        const int k0 = kt * 32;
        #pragma unroll
        for (int j = 0; j < 2; j++) {
            int idx = j * 256 + tid;
            int r   = idx >> 2;
            int ch  = idx & 3;
            int pkk = toks[r];
            const __half* src = (pkk >= 0)
                ? &g_h[(size_t)pkk * I_DIM + k0 + ch * 8] : g_h;
            cp16(H0 + buf * STG + r * PITCH + ch * 16, src, pkk >= 0);
        }
    };
    auto ldgW = [&](int kt) {
        const int k0 = kt * 32;
        #pragma unroll
        for (int j = 0; j < 2; j++) {
            int idx = j * 256 + tid;
            int r   = idx >> 2;
            int ch  = idx & 3;
            const float* s = &wdE[(size_t)r * I_DIM + k0 + ch * 8];
            dq[j * 2]     = *(const float4*)s;
            dq[j * 2 + 1] = *(const float4*)(s + 4);
        }
    };
    auto stsW = [&](int buf) {
        #pragma unroll
        for (int j = 0; j < 2; j++) {
            int idx = j * 256 + tid;
            int r   = idx >> 2;
            int ch  = idx & 3;
            uint32_t a = D0 + buf * STG + r * PITCH + ch * 16;
            sts128(a, pk2(dq[j*2].x, dq[j*2].y), pk2(dq[j*2].z, dq[j*2].w),
                      pk2(dq[j*2+1].x, dq[j*2+1].y), pk2(dq[j*2+1].z, dq[j*2+1].w));
        }
    };

    const int KT = I_DIM / 32;   // 24
    ldgH(0, 0); CP_COMMIT();
    ldgW(0);

    for (int kt = 0; kt < KT; kt++) {
        const int buf = kt & 1;
        stsW(buf);
        CP_WAIT0();
        __syncthreads();
        if (kt + 1 < KT) {
            ldgH(kt + 1, buf ^ 1); CP_COMMIT();
            ldgW(kt + 1);
        }

        const uint32_t Hb = H0 + buf * STG + aoff;
        const uint32_t Db = D0 + buf * STG + boff;

        #pragma unroll
        for (int kc = 0; kc < 2; kc++) {
            const uint32_t kb = kc * 32;
            uint32_t a[4][4];
            #pragma unroll
            for (int mf = 0; mf < 4; mf++) ldsm4(a[mf], Hb + mf * 16 * PITCH + kb);
            uint32_t b[4][2];
            #pragma unroll
            for (int nf = 0; nf < 4; nf++) ldsm2(b[nf], Db + nf * 8 * PITCH + kb);
            #pragma unroll
            for (int mf = 0; mf < 4; mf++)
                #pragma unroll
                for (int nf = 0; nf < 4; nf++)
                    mma16(acc[mf][nf], a[mf], b[nf]);
        }
    }

    // epilogue: exact per-row fp32 store
    #pragma unroll
    for (int mf = 0; mf < 4; mf++) {
        #pragma unroll
        for (int half = 0; half < 2; half++) {
            int rl = mw0 + mf * 16 + gid + half * 8;
            int pkk = toks[rl];
            if (pkk < 0) continue;
            #pragma unroll
            for (int nf = 0; nf < 4; nf++) {
                int c = col0 + nw0 + nf * 8 + 2 * tcol;
                float2 o;
                o.x = acc[mf][nf][half * 2 + 0];
                o.y = acc[mf][nf][half * 2 + 1];
                *(float2*)&g_o[(size_t)pkk * H_DIM + c] = o;
            }
        }
    }
}

// -------- reduce: out[t] = sum_s g_o[t*8+s] ----------------------------------
__global__ __launch_bounds__(256) void reduce_kernel(float* __restrict__ out)
{
    int id = blockIdx.x * 256 + threadIdx.x;
    int t  = id >> 9;
    int c4 = id & 511;
    const float4* b = (const float4*)(g_o + (size_t)t * TOPK * H_DIM) + c4;
    float4 s = b[0];
    #pragma unroll
    for (int sl = 1; sl < TOPK; sl++) {
        float4 v = b[(size_t)sl * (H_DIM / 4)];
        s.x += v.x; s.y += v.y; s.z += v.z; s.w += v.w;
    }
    ((float4*)out)[id] = s;
}

// ---------------------------------------------------------------------------
extern "C" void kernel_launch(void* const* d_in, const int* in_sizes, int n_in,
                              void* d_out, int out_size)
{
    const float* x  = (const float*)d_in[0];
    const float* gw = (const float*)d_in[1];
    const float* wg = (const float*)d_in[2];
    const float* wu = (const float*)d_in[3];
    const float* wd = (const float*)d_in[4];
    float* out = (float*)d_out;

    const int smemAB = 2 * 20480;   // 40960 B
    static bool attr_done = false;
    if (!attr_done) {
        cudaFuncSetAttribute(phaseA_kernel, cudaFuncAttributeMaxDynamicSharedMemorySize, smemAB);
        cudaFuncSetAttribute(phaseB_kernel, cudaFuncAttributeMaxDynamicSharedMemorySize, smemAB);
        attr_done = true;
    }

    init_kernel<<<1, 32>>>();
    xh_kernel<<<(T_TOK * H_DIM / 8) / 256, 256>>>(x);
    router_kernel<<<T_TOK, 256>>>(x, gw);
    phaseA_kernel<<<dim3(16, I_DIM / 64, N_EXP), 256, smemAB>>>(wg, wu);
    phaseB_kernel<<<dim3(16, H_DIM / 128, N_EXP), 256, smemAB>>>(wd);
    reduce_kernel<<<(T_TOK * (H_DIM / 4)) / 256, 256>>>(out);
}